// round 6
// baseline (speedup 1.0000x reference)
#include <cuda_runtime.h>

#define DIM    1024
#define BATCH  2
#define SEQ    2048
#define NHEADS 16
#define DH     64
#define TOKENS (BATCH*SEQ)      // 4096
#define QKV_N  (3*DIM)          // 3072

// Scratch (allocation-free rule: __device__ globals)
__device__ float g_q[BATCH*NHEADS*SEQ*DH];   // [b,h,n,d]
__device__ float g_k[BATCH*NHEADS*SEQ*DH];
__device__ float g_v[BATCH*NHEADS*SEQ*DH];
__device__ float g_o[TOKENS*DIM];            // [b,n,c]  attention output

// ---------------------------------------------------------------------------
// GEMM: C[M,Nout] = A[M,K] @ W[Nout,K]^T + bias
// BM=BN=64, BK=16, 256 threads, 4x4 micro-tile per thread.
// MODE 0: A = x, epilogue scatters qkv -> g_q/g_k/g_v in [b,h,n,d] layout
// MODE 1: A = g_o (internal), epilogue writes C[m*Nout + j] directly
// ---------------------------------------------------------------------------
template<int MODE>
__global__ __launch_bounds__(256)
void gemm64(const float* __restrict__ A, const float* __restrict__ W,
            const float* __restrict__ bias, float* __restrict__ C,
            int K, int Nout)
{
    __shared__ float As[16][64];   // As[k][m]
    __shared__ float Bs[16][64];   // Bs[k][n]

    const int tid = threadIdx.x;
    const int tx  = tid & 15;
    const int ty  = tid >> 4;
    const int m0  = blockIdx.y << 6;
    const int n0  = blockIdx.x << 6;
    const int lr  = tid >> 2;      // 0..63 row within tile
    const int lq  = tid & 3;       // k-quad

    const float* Abase = (MODE == 1) ? (const float*)g_o : A;
    const float* Ag = Abase + (size_t)(m0 + lr) * K + lq * 4;
    const float* Wg = W     + (size_t)(n0 + lr) * K + lq * 4;

    float acc[4][4] = {};

    for (int k0 = 0; k0 < K; k0 += 16) {
        float4 av = *reinterpret_cast<const float4*>(Ag + k0);
        float4 wv = *reinterpret_cast<const float4*>(Wg + k0);
        __syncthreads();   // protect previous iteration's compute reads
        As[lq*4+0][lr] = av.x; As[lq*4+1][lr] = av.y;
        As[lq*4+2][lr] = av.z; As[lq*4+3][lr] = av.w;
        Bs[lq*4+0][lr] = wv.x; Bs[lq*4+1][lr] = wv.y;
        Bs[lq*4+2][lr] = wv.z; Bs[lq*4+3][lr] = wv.w;
        __syncthreads();

#pragma unroll
        for (int k = 0; k < 16; ++k) {
            float4 a = *reinterpret_cast<const float4*>(&As[k][ty*4]);
            float4 b = *reinterpret_cast<const float4*>(&Bs[k][tx*4]);
            float ar[4] = {a.x, a.y, a.z, a.w};
            float br[4] = {b.x, b.y, b.z, b.w};
#pragma unroll
            for (int i = 0; i < 4; ++i)
#pragma unroll
                for (int j = 0; j < 4; ++j)
                    acc[i][j] = fmaf(ar[i], br[j], acc[i][j]);
        }
    }

#pragma unroll
    for (int i = 0; i < 4; ++i) {
        const int m = m0 + ty*4 + i;
#pragma unroll
        for (int j = 0; j < 4; ++j) {
            const int jg = n0 + tx*4 + j;
            const float v = acc[i][j] + bias[jg];
            if (MODE == 0) {
                // qkv reshape(B,N,3,H,Dh): jg -> (c3, h, d); m -> (b, n)
                const int c3  = jg >> 10;
                const int rem = jg & 1023;
                const int h   = rem >> 6;
                const int d   = rem & 63;
                const int b   = m >> 11;
                const int n   = m & 2047;
                const int dst = ((b*NHEADS + h)*SEQ + n)*DH + d;
                float* p = (c3 == 0) ? g_q : (c3 == 1) ? g_k : g_v;
                p[dst] = v;
            } else {
                C[(size_t)m * Nout + jg] = v;
            }
        }
    }
}

// ---------------------------------------------------------------------------
// Flash attention: per block one (b,h) pair and 64 queries; iterate 32 key
// tiles of 64. Online softmax; O accumulated in registers (4x4 per thread).
// smem: Qt[d][i], Kt[d][j] (transposed, float4 reads), Ps[i][j], Vs[j][d].
// ---------------------------------------------------------------------------
__global__ __launch_bounds__(256)
void attn64()
{
    extern __shared__ float sm[];
    float* Qt = sm;            // 64*64  Qt[d*64 + i]
    float* Kt = sm + 4096;     // 64*64  Kt[d*64 + j]
    float* Ps = sm + 8192;     // 64*64  Ps[i*64 + j]
    float* Vs = sm + 12288;    // 64*64  Vs[j*64 + d]

    const int tid = threadIdx.x;
    const int tx  = tid & 15;
    const int ty  = tid >> 4;
    const int bh  = blockIdx.y;        // b*NHEADS + h
    const int q0  = blockIdx.x << 6;
    const float scale = 0.125f;        // Dh^-0.5 = 1/8

    const float* Qg = g_q + (size_t)bh * SEQ * DH;
    const float* Kg = g_k + (size_t)bh * SEQ * DH;
    const float* Vg = g_v + (size_t)bh * SEQ * DH;

    const int lr = tid >> 2;   // 0..63 row
    const int lq = tid & 3;    // handles d = lq*16 .. lq*16+15

    // Load Q tile once, fold in scale, store transposed
#pragma unroll
    for (int c = 0; c < 4; ++c) {
        const int d = lq*16 + c*4;
        float4 v = *reinterpret_cast<const float4*>(Qg + (q0 + lr)*DH + d);
        Qt[(d+0)*64 + lr] = v.x * scale;
        Qt[(d+1)*64 + lr] = v.y * scale;
        Qt[(d+2)*64 + lr] = v.z * scale;
        Qt[(d+3)*64 + lr] = v.w * scale;
    }

    float o[4][4]  = {};
    float mrow[4]  = {-1e30f, -1e30f, -1e30f, -1e30f};
    float lsum[4]  = {};

    for (int kt = 0; kt < SEQ; kt += 64) {
        __syncthreads();   // previous AV done (Vs/Ps free), Qt visible on iter 0
#pragma unroll
        for (int c = 0; c < 4; ++c) {
            const int d = lq*16 + c*4;
            float4 kv = *reinterpret_cast<const float4*>(Kg + (kt + lr)*DH + d);
            Kt[(d+0)*64 + lr] = kv.x;
            Kt[(d+1)*64 + lr] = kv.y;
            Kt[(d+2)*64 + lr] = kv.z;
            Kt[(d+3)*64 + lr] = kv.w;
            float4 vv = *reinterpret_cast<const float4*>(Vg + (kt + lr)*DH + d);
            *reinterpret_cast<float4*>(&Vs[lr*64 + d]) = vv;
        }
        __syncthreads();

        // S = (Q*scale) @ K^T, 4x4 per thread
        float s[4][4] = {};
#pragma unroll 4
        for (int d = 0; d < 64; ++d) {
            float4 a = *reinterpret_cast<const float4*>(&Qt[d*64 + ty*4]);
            float4 b = *reinterpret_cast<const float4*>(&Kt[d*64 + tx*4]);
            float ar[4] = {a.x, a.y, a.z, a.w};
            float br[4] = {b.x, b.y, b.z, b.w};
#pragma unroll
            for (int i = 0; i < 4; ++i)
#pragma unroll
                for (int j = 0; j < 4; ++j)
                    s[i][j] = fmaf(ar[i], br[j], s[i][j]);
        }

        // Online softmax: row groups are the 16-lane halves (tx dimension)
#pragma unroll
        for (int i = 0; i < 4; ++i) {
            float mx = fmaxf(fmaxf(s[i][0], s[i][1]), fmaxf(s[i][2], s[i][3]));
            mx = fmaxf(mx, __shfl_xor_sync(0xffffffffu, mx, 1));
            mx = fmaxf(mx, __shfl_xor_sync(0xffffffffu, mx, 2));
            mx = fmaxf(mx, __shfl_xor_sync(0xffffffffu, mx, 4));
            mx = fmaxf(mx, __shfl_xor_sync(0xffffffffu, mx, 8));
            const float mnew = fmaxf(mrow[i], mx);
            const float corr = __expf(mrow[i] - mnew);
            mrow[i] = mnew;
            float ps = 0.f;
#pragma unroll
            for (int j = 0; j < 4; ++j) {
                const float p = __expf(s[i][j] - mnew);
                s[i][j] = p;
                ps += p;
            }
            ps += __shfl_xor_sync(0xffffffffu, ps, 1);
            ps += __shfl_xor_sync(0xffffffffu, ps, 2);
            ps += __shfl_xor_sync(0xffffffffu, ps, 4);
            ps += __shfl_xor_sync(0xffffffffu, ps, 8);
            lsum[i] = lsum[i]*corr + ps;
#pragma unroll
            for (int j = 0; j < 4; ++j) o[i][j] *= corr;
        }

        // Store P natural layout (conflict-free float4 STS)
#pragma unroll
        for (int i = 0; i < 4; ++i) {
            float4 pv = make_float4(s[i][0], s[i][1], s[i][2], s[i][3]);
            *reinterpret_cast<float4*>(&Ps[(ty*4+i)*64 + tx*4]) = pv;
        }
        __syncthreads();

        // O += P @ V (P reads are warp broadcasts; V reads float4 conflict-free)
#pragma unroll 4
        for (int j = 0; j < 64; ++j) {
            float pa[4];
#pragma unroll
            for (int i = 0; i < 4; ++i) pa[i] = Ps[(ty*4+i)*64 + j];
            float4 vb = *reinterpret_cast<const float4*>(&Vs[j*64 + tx*4]);
            float br[4] = {vb.x, vb.y, vb.z, vb.w};
#pragma unroll
            for (int i = 0; i < 4; ++i)
#pragma unroll
                for (int jj = 0; jj < 4; ++jj)
                    o[i][jj] = fmaf(pa[i], br[jj], o[i][jj]);
        }
    }

    // Normalize + write to [b, n, h*64+d]
    const int b = bh >> 4;
    const int h = bh & 15;
#pragma unroll
    for (int i = 0; i < 4; ++i) {
        const float inv = 1.0f / lsum[i];
        const int n = q0 + ty*4 + i;
        float4 ov = make_float4(o[i][0]*inv, o[i][1]*inv, o[i][2]*inv, o[i][3]*inv);
        *reinterpret_cast<float4*>(
            &g_o[((size_t)(b*SEQ + n))*DIM + h*DH + tx*4]) = ov;
    }
}

// ---------------------------------------------------------------------------
// Launch: 3 kernels on the default stream (graph-capturable, allocation-free)
// ---------------------------------------------------------------------------
extern "C" void kernel_launch(void* const* d_in, const int* in_sizes, int n_in,
                              void* d_out, int out_size)
{
    const float* x      = (const float*)d_in[0];   // [2,2048,1024]
    const float* qkv_w  = (const float*)d_in[1];   // [3072,1024]
    const float* qkv_b  = (const float*)d_in[2];   // [3072]
    const float* proj_w = (const float*)d_in[3];   // [1024,1024]
    const float* proj_b = (const float*)d_in[4];   // [1024]
    float* out = (float*)d_out;                    // [2,2048,1024]

    // attn64 needs 64 KB dynamic smem (> 48 KB static limit). Idempotent,
    // host-side (non-stream) call; safe under graph capture.
    cudaFuncSetAttribute(attn64, cudaFuncAttributeMaxDynamicSharedMemorySize,
                         65536);

    dim3 blk(256);

    // 1) QKV projection + bias + scatter into [b,h,n,d] Q/K/V
    gemm64<0><<<dim3(QKV_N/64, TOKENS/64), blk>>>(
        x, qkv_w, qkv_b, nullptr, DIM, QKV_N);

    // 2) Attention (flash, online softmax) -> g_o [b,n,c]
    attn64<<<dim3(SEQ/64, BATCH*NHEADS), blk, 65536>>>();

    // 3) Output projection + bias -> d_out
    gemm64<1><<<dim3(DIM/64, TOKENS/64), blk>>>(
        nullptr, proj_w, proj_b, out, DIM, DIM);
}

// round 7
// speedup vs baseline: 1.2420x; 1.2420x over previous
#include <cuda_runtime.h>

#define DIM    1024
#define BATCH  2
#define SEQ    2048
#define NHEADS 16
#define DH     64
#define TOKENS (BATCH*SEQ)      // 4096
#define QKV_N  (3*DIM)          // 3072

// Scratch (allocation-free rule: __device__ globals)
__device__ float g_q[BATCH*NHEADS*SEQ*DH];   // [b,h,n,d]
__device__ float g_k[BATCH*NHEADS*SEQ*DH];
__device__ float g_v[BATCH*NHEADS*SEQ*DH];
__device__ float g_o[TOKENS*DIM];            // [b,n,c]  attention output

// ---------------------------------------------------------------------------
// GEMM: C[M,Nout] = A[M,K] @ W[Nout,K]^T + bias
// BM=BN=128, BK=16, 256 threads, 8x8 register micro-tile.
// 4 LDS.128 per 64 FMA (vs 2 per 16 in R5) -> FMA-bound, not L1-bound.
// MODE 0: A = x, epilogue scatters qkv -> g_q/g_k/g_v in [b,h,n,d] layout
// MODE 1: A = g_o (internal), epilogue writes C[m*Nout + j] directly
// ---------------------------------------------------------------------------
template<int MODE>
__global__ __launch_bounds__(256, 2)
void gemm128(const float* __restrict__ A, const float* __restrict__ W,
             const float* __restrict__ bias, float* __restrict__ C,
             int K, int Nout)
{
    __shared__ float As[16][132];   // As[k][m], stride 132 keeps f4 align + banks
    __shared__ float Bs[16][132];   // Bs[k][n]

    const int tid = threadIdx.x;
    const int tx  = tid & 15;
    const int ty  = tid >> 4;
    const int m0  = blockIdx.y << 7;
    const int n0  = blockIdx.x << 7;
    const int r0  = tid >> 2;         // 0..63
    const int kq  = (tid & 3) << 2;   // 0,4,8,12

    const float* Abase = (MODE == 1) ? (const float*)g_o : A;
    const float* Ag0 = Abase + (size_t)(m0 + r0)      * K + kq;
    const float* Ag1 = Abase + (size_t)(m0 + r0 + 64) * K + kq;
    const float* Wg0 = W     + (size_t)(n0 + r0)      * K + kq;
    const float* Wg1 = W     + (size_t)(n0 + r0 + 64) * K + kq;

    float acc[8][8] = {};

    // Prefetch first tile into registers
    float4 a0 = *reinterpret_cast<const float4*>(Ag0);
    float4 a1 = *reinterpret_cast<const float4*>(Ag1);
    float4 b0 = *reinterpret_cast<const float4*>(Wg0);
    float4 b1 = *reinterpret_cast<const float4*>(Wg1);

    for (int k0 = 0; k0 < K; k0 += 16) {
        __syncthreads();   // previous tile's compute reads done
        As[kq+0][r0]    = a0.x; As[kq+1][r0]    = a0.y;
        As[kq+2][r0]    = a0.z; As[kq+3][r0]    = a0.w;
        As[kq+0][r0+64] = a1.x; As[kq+1][r0+64] = a1.y;
        As[kq+2][r0+64] = a1.z; As[kq+3][r0+64] = a1.w;
        Bs[kq+0][r0]    = b0.x; Bs[kq+1][r0]    = b0.y;
        Bs[kq+2][r0]    = b0.z; Bs[kq+3][r0]    = b0.w;
        Bs[kq+0][r0+64] = b1.x; Bs[kq+1][r0+64] = b1.y;
        Bs[kq+2][r0+64] = b1.z; Bs[kq+3][r0+64] = b1.w;
        __syncthreads();

        if (k0 + 16 < K) {   // prefetch next tile (overlaps compute)
            a0 = *reinterpret_cast<const float4*>(Ag0 + k0 + 16);
            a1 = *reinterpret_cast<const float4*>(Ag1 + k0 + 16);
            b0 = *reinterpret_cast<const float4*>(Wg0 + k0 + 16);
            b1 = *reinterpret_cast<const float4*>(Wg1 + k0 + 16);
        }

#pragma unroll
        for (int k = 0; k < 16; ++k) {
            float4 x0 = *reinterpret_cast<const float4*>(&As[k][ty*8]);
            float4 x1 = *reinterpret_cast<const float4*>(&As[k][ty*8+4]);
            float4 y0 = *reinterpret_cast<const float4*>(&Bs[k][tx*8]);
            float4 y1 = *reinterpret_cast<const float4*>(&Bs[k][tx*8+4]);
            float ar[8] = {x0.x,x0.y,x0.z,x0.w, x1.x,x1.y,x1.z,x1.w};
            float br[8] = {y0.x,y0.y,y0.z,y0.w, y1.x,y1.y,y1.z,y1.w};
#pragma unroll
            for (int i = 0; i < 8; ++i)
#pragma unroll
                for (int j = 0; j < 8; ++j)
                    acc[i][j] = fmaf(ar[i], br[j], acc[i][j]);
        }
    }

#pragma unroll
    for (int i = 0; i < 8; ++i) {
        const int m = m0 + ty*8 + i;
#pragma unroll
        for (int j = 0; j < 8; ++j) {
            const int jg = n0 + tx*8 + j;
            const float v = acc[i][j] + bias[jg];
            if (MODE == 0) {
                // qkv reshape(B,N,3,H,Dh): jg -> (c3, h, d); m -> (b, n)
                const int c3  = jg >> 10;
                const int rem = jg & 1023;
                const int h   = rem >> 6;
                const int d   = rem & 63;
                const int b   = m >> 11;
                const int n   = m & 2047;
                const int dst = ((b*NHEADS + h)*SEQ + n)*DH + d;
                float* p = (c3 == 0) ? g_q : (c3 == 1) ? g_k : g_v;
                p[dst] = v;
            } else {
                C[(size_t)m * Nout + jg] = v;
            }
        }
    }
}

// ---------------------------------------------------------------------------
// Flash attention: Br=128 queries per block, Bc=64 keys per tile, 256 threads.
// Thread grid 16(ty) x 16(tx); micro-tile 8 rows x 4 cols.
// Q,K stored d-major (transposed) in smem -> S GEMM is 3 LDS.128 per 32 FMA.
// P stored natural, consumed in j-chunks of 4 -> 12 LDS.128 per 128 FMA.
// smem: Qt[64][132] + Kt[64][64] + Vs[64][64] + Ps[128][64] = 97 KB (2 CTA/SM)
// ---------------------------------------------------------------------------
#define QT_STRIDE 132
#define ATTN_SMEM ((64*QT_STRIDE + 64*64 + 64*64 + 128*64) * 4)

__global__ __launch_bounds__(256)
void attn128()
{
    extern __shared__ float sm[];
    float* Qt = sm;                        // [64][132]  d-major, scale folded
    float* Kt = sm + 64*QT_STRIDE;         // [64][64]   d-major
    float* Vs = Kt + 64*64;                // [64][64]   natural [j][d]
    float* Ps = Vs + 64*64;                // [128][64]  natural [i][j]

    const int tid = threadIdx.x;
    const int tx  = tid & 15;
    const int ty  = tid >> 4;
    const int bh  = blockIdx.y;            // b*NHEADS + h
    const int q0  = blockIdx.x << 7;

    const float* Qg = g_q + (size_t)bh * SEQ * DH;
    const float* Kg = g_k + (size_t)bh * SEQ * DH;
    const float* Vg = g_v + (size_t)bh * SEQ * DH;

    // Load Q tile transposed, fold in scale = Dh^-0.5 = 0.125
    {
        const int r   = tid >> 1;          // 0..127
        const int c0  = (tid & 1) * 32;    // col half
#pragma unroll
        for (int v = 0; v < 8; ++v) {
            const int d = c0 + v*4;
            float4 q4 = *reinterpret_cast<const float4*>(
                Qg + (size_t)(q0 + r)*DH + d);
            Qt[(d+0)*QT_STRIDE + r] = q4.x * 0.125f;
            Qt[(d+1)*QT_STRIDE + r] = q4.y * 0.125f;
            Qt[(d+2)*QT_STRIDE + r] = q4.z * 0.125f;
            Qt[(d+3)*QT_STRIDE + r] = q4.w * 0.125f;
        }
    }

    float o[8][4]  = {};
    float mrow[8], lsum[8] = {};
#pragma unroll
    for (int i = 0; i < 8; ++i) mrow[i] = -1e30f;

    const int kr = tid >> 2;          // 0..63 key row
    const int kc = (tid & 3) * 16;    // col base (16 wide)

    for (int kt = 0; kt < SEQ; kt += 64) {
        // Prefetch K,V gmem -> regs (overlaps prior PV tail)
        float4 kv[4], vv[4];
#pragma unroll
        for (int v = 0; v < 4; ++v) {
            kv[v] = *reinterpret_cast<const float4*>(
                Kg + (size_t)(kt + kr)*DH + kc + v*4);
            vv[v] = *reinterpret_cast<const float4*>(
                Vg + (size_t)(kt + kr)*DH + kc + v*4);
        }
        __syncthreads();   // prev PV done -> Kt/Vs free (also Qt visible, iter 0)
#pragma unroll
        for (int v = 0; v < 4; ++v) {
            const int d = kc + v*4;
            Kt[(d+0)*64 + kr] = kv[v].x;
            Kt[(d+1)*64 + kr] = kv[v].y;
            Kt[(d+2)*64 + kr] = kv[v].z;
            Kt[(d+3)*64 + kr] = kv[v].w;
            *reinterpret_cast<float4*>(&Vs[kr*64 + d]) = vv[v];
        }
        __syncthreads();

        // S = (Q*scale) @ K^T  (8x4 per thread)
        float s[8][4] = {};
#pragma unroll 8
        for (int d = 0; d < 64; ++d) {
            float4 x0 = *reinterpret_cast<const float4*>(&Qt[d*QT_STRIDE + ty*8]);
            float4 x1 = *reinterpret_cast<const float4*>(&Qt[d*QT_STRIDE + ty*8 + 4]);
            float4 y  = *reinterpret_cast<const float4*>(&Kt[d*64 + tx*4]);
            float ar[8] = {x0.x,x0.y,x0.z,x0.w, x1.x,x1.y,x1.z,x1.w};
            float br[4] = {y.x, y.y, y.z, y.w};
#pragma unroll
            for (int i = 0; i < 8; ++i)
#pragma unroll
                for (int j = 0; j < 4; ++j)
                    s[i][j] = fmaf(ar[i], br[j], s[i][j]);
        }

        // Online softmax: rows reduce across tx lanes (lane bits 0..3)
#pragma unroll
        for (int i = 0; i < 8; ++i) {
            float mx = fmaxf(fmaxf(s[i][0], s[i][1]), fmaxf(s[i][2], s[i][3]));
            mx = fmaxf(mx, __shfl_xor_sync(0xffffffffu, mx, 1));
            mx = fmaxf(mx, __shfl_xor_sync(0xffffffffu, mx, 2));
            mx = fmaxf(mx, __shfl_xor_sync(0xffffffffu, mx, 4));
            mx = fmaxf(mx, __shfl_xor_sync(0xffffffffu, mx, 8));
            const float mnew = fmaxf(mrow[i], mx);
            const float corr = __expf(mrow[i] - mnew);
            mrow[i] = mnew;
            float ps = 0.f;
#pragma unroll
            for (int j = 0; j < 4; ++j) {
                const float p = __expf(s[i][j] - mnew);
                s[i][j] = p;
                ps += p;
            }
            ps += __shfl_xor_sync(0xffffffffu, ps, 1);
            ps += __shfl_xor_sync(0xffffffffu, ps, 2);
            ps += __shfl_xor_sync(0xffffffffu, ps, 4);
            ps += __shfl_xor_sync(0xffffffffu, ps, 8);
            lsum[i] = lsum[i]*corr + ps;
#pragma unroll
            for (int j = 0; j < 4; ++j) o[i][j] *= corr;
        }

        // Store P (natural layout, conflict-free float4 STS)
#pragma unroll
        for (int i = 0; i < 8; ++i)
            *reinterpret_cast<float4*>(&Ps[(ty*8+i)*64 + tx*4]) =
                make_float4(s[i][0], s[i][1], s[i][2], s[i][3]);
        __syncthreads();

        // O += P @ V  (j in chunks of 4: 12 LDS.128 per 128 FMA)
#pragma unroll 2
        for (int j0 = 0; j0 < 64; j0 += 4) {
            float vr[4][4];
#pragma unroll
            for (int jj = 0; jj < 4; ++jj) {
                float4 v4 = *reinterpret_cast<const float4*>(
                    &Vs[(j0+jj)*64 + tx*4]);
                vr[jj][0] = v4.x; vr[jj][1] = v4.y;
                vr[jj][2] = v4.z; vr[jj][3] = v4.w;
            }
#pragma unroll
            for (int i = 0; i < 8; ++i) {
                float4 p4 = *reinterpret_cast<const float4*>(
                    &Ps[(ty*8+i)*64 + j0]);
                float pv[4] = {p4.x, p4.y, p4.z, p4.w};
#pragma unroll
                for (int jj = 0; jj < 4; ++jj)
#pragma unroll
                    for (int dd = 0; dd < 4; ++dd)
                        o[i][dd] = fmaf(pv[jj], vr[jj][dd], o[i][dd]);
            }
        }
    }

    // Normalize + write to g_o [b, n, h*64+d]
    const int b = bh >> 4;
    const int h = bh & 15;
#pragma unroll
    for (int i = 0; i < 8; ++i) {
        const float inv = 1.0f / lsum[i];
        const int n = q0 + ty*8 + i;
        float4 ov = make_float4(o[i][0]*inv, o[i][1]*inv,
                                o[i][2]*inv, o[i][3]*inv);
        *reinterpret_cast<float4*>(
            &g_o[((size_t)(b*SEQ + n))*DIM + h*DH + tx*4]) = ov;
    }
}

// ---------------------------------------------------------------------------
// Launch: 3 kernels on the default stream (graph-capturable, allocation-free)
// ---------------------------------------------------------------------------
extern "C" void kernel_launch(void* const* d_in, const int* in_sizes, int n_in,
                              void* d_out, int out_size)
{
    const float* x      = (const float*)d_in[0];   // [2,2048,1024]
    const float* qkv_w  = (const float*)d_in[1];   // [3072,1024]
    const float* qkv_b  = (const float*)d_in[2];   // [3072]
    const float* proj_w = (const float*)d_in[3];   // [1024,1024]
    const float* proj_b = (const float*)d_in[4];   // [1024]
    float* out = (float*)d_out;                    // [2,2048,1024]

    cudaFuncSetAttribute(attn128, cudaFuncAttributeMaxDynamicSharedMemorySize,
                         ATTN_SMEM);

    dim3 blk(256);

    // 1) QKV projection + bias + scatter into [b,h,n,d] Q/K/V
    gemm128<0><<<dim3(QKV_N/128, TOKENS/128), blk>>>(
        x, qkv_w, qkv_b, nullptr, DIM, QKV_N);

    // 2) Attention (flash, online softmax) -> g_o [b,n,c]
    attn128<<<dim3(SEQ/128, BATCH*NHEADS), blk, ATTN_SMEM>>>();

    // 3) Output projection + bias -> d_out
    gemm128<1><<<dim3(DIM/128, TOKENS/128), blk>>>(
        nullptr, proj_w, proj_b, out, DIM, DIM);
}